// round 9
// baseline (speedup 1.0000x reference)
#include <cuda_runtime.h>
#include <cstdint>

// ============================================================================
// Gram matrix C = A^T A.  A: [8192, 4096] fp32 row-major. C: [4096, 4096] fp32.
// Pass 1: transpose+convert A -> At (tf32, [4096][8192]) in __device__ scratch.
// Pass 2: GEMM via mma.sync m16n8k8 tf32, cp.async 4-stage pipeline, ONE
//         __syncthreads per k-chunk, 128x256 CTA tile, lower-triangle grid.
// R6/R8: 512 threads / 16 warps (warp tile 64x32) -> 4 warps/SMSP for latency
//        hiding; acc 64 regs/thread.  (Resubmission: R7 died to broker infra.)
// ============================================================================

#define NDIM 4096
#define KDIM 8192
#define BM 128
#define BN 256
#define BK 32
#define NCH (KDIM / BK)       // 256 k-chunks
#define THREADS 512
#define ROWB 144              // 32 floats + 16B pad -> conflict-free LDSM/STS
#define STAGES 4

static constexpr int A_STAGE_B = BM * ROWB;             // 18432
static constexpr int B_STAGE_B = BN * ROWB;             // 36864
static constexpr int STAGE_B   = A_STAGE_B + B_STAGE_B; // 55296
static constexpr int SMEM_TOTAL = STAGES * STAGE_B;     // 221184

__device__ uint32_t g_AT[(size_t)NDIM * KDIM];          // 128MB tf32 scratch

__device__ __forceinline__ uint32_t smem_u32(const void* p) {
    uint32_t a;
    asm("{ .reg .u64 t; cvta.to.shared.u64 t, %1; cvt.u32.u64 %0, t; }"
        : "=r"(a) : "l"(p));
    return a;
}

__device__ __forceinline__ uint32_t f2tf32(float f) {
    uint32_t u;
    asm("cvt.rna.tf32.f32 %0, %1;" : "=r"(u) : "f"(f));
    return u;
}

__device__ __forceinline__ void ldsm4(uint32_t& r0, uint32_t& r1,
                                      uint32_t& r2, uint32_t& r3, uint32_t addr) {
    asm volatile("ldmatrix.sync.aligned.m8n8.x4.shared.b16 {%0,%1,%2,%3}, [%4];"
                 : "=r"(r0), "=r"(r1), "=r"(r2), "=r"(r3) : "r"(addr));
}

__device__ __forceinline__ void mma_tf32(float* c, const uint32_t* a, const uint32_t* b) {
    asm volatile(
        "mma.sync.aligned.m16n8k8.row.col.f32.tf32.tf32.f32 "
        "{%0,%1,%2,%3}, {%4,%5,%6,%7}, {%8,%9}, {%0,%1,%2,%3};"
        : "+f"(c[0]), "+f"(c[1]), "+f"(c[2]), "+f"(c[3])
        : "r"(a[0]), "r"(a[1]), "r"(a[2]), "r"(a[3]), "r"(b[0]), "r"(b[1]));
}

__device__ __forceinline__ void cp16(uint32_t dst, const void* src) {
    asm volatile("cp.async.cg.shared.global [%0], [%1], 16;"
                 :: "r"(dst), "l"(src) : "memory");
}

// ---------------------------------------------------------------------------
// Pass 1: At[n][k] = tf32(inp[k][n]).  32x32 smem tiles, block (32,8).
// ---------------------------------------------------------------------------
__global__ __launch_bounds__(256) void transpose_cvt_kernel(
        const float* __restrict__ inp) {
    __shared__ float tile[32][33];
    const int tx = threadIdx.x, ty = threadIdx.y;
    const int n0 = blockIdx.x * 32;
    const int k0 = blockIdx.y * 32;
#pragma unroll
    for (int j = 0; j < 4; ++j)
        tile[ty + j * 8][tx] = inp[(size_t)(k0 + ty + j * 8) * NDIM + n0 + tx];
    __syncthreads();
#pragma unroll
    for (int j = 0; j < 4; ++j)
        g_AT[(size_t)(n0 + ty + j * 8) * KDIM + k0 + tx] =
            f2tf32(tile[tx][ty + j * 8]);
}

// ---------------------------------------------------------------------------
// Pass 2: GEMM.  16 warps: wm = wid>>3 (2 x 64 rows), wn = wid&7 (8 x 32 cols)
// ---------------------------------------------------------------------------
__global__ __launch_bounds__(THREADS, 1)
void gram_mma_kernel(float* __restrict__ out) {
    extern __shared__ char smem[];
    const uint32_t sbase = smem_u32(smem);
    const int tid  = threadIdx.x;
    const int lane = tid & 31;
    const int wid  = tid >> 5;
    const int wm   = wid >> 3;      // 0..1  (m position, 64 rows)
    const int wn   = wid & 7;       // 0..7  (n position, 32 cols)

    // lower-triangle tile decode: (bi,bj) with bi >= 2*bj on 32(m) x 16(n) grid
    int t = (int)blockIdx.x, bj = 0;
    while (t >= 32 - 2 * bj) { t -= 32 - 2 * bj; ++bj; }
    const int bi = 2 * bj + t;
    const int i0 = bi * BM;
    const int j0 = bj * BN;

    // ldmatrix address components (tf32 frags via b16 x4)
    const int g = lane >> 3, r8 = lane & 7;
    const int a_row = wm * 64 + ((g & 1) << 3) + r8;
    const uint32_t a_kb = (uint32_t)((g >> 1) << 4);
    const int b_row = wn * 32 + ((g >> 1) << 3) + r8;
    const uint32_t b_kb = (uint32_t)((g & 1) << 4);

    // cp.async task decode: A = 1024 16B-chunks (128m x 8kg) -> 2/thread,
    // B = 2048 -> 4/thread.  8 consecutive threads cover one 128B k-segment.
    int am[2], ak[2];
    int bm_[4], bk[4];
#pragma unroll
    for (int s = 0; s < 2; ++s) { int a = tid + THREADS * s; am[s] = a >> 3; ak[s] = a & 7; }
#pragma unroll
    for (int s = 0; s < 4; ++s) { int b = tid + THREADS * s; bm_[s] = b >> 3; bk[s] = b & 7; }

    const uint32_t* At = g_AT;

    auto issue_chunk = [&](int c) {
        const uint32_t st = sbase + (c & (STAGES - 1)) * STAGE_B;
        const size_t kbase = (size_t)c * BK;
#pragma unroll
        for (int s = 0; s < 2; ++s)
            cp16(st + (uint32_t)(am[s] * ROWB + ak[s] * 16),
                 At + (size_t)(i0 + am[s]) * KDIM + kbase + ak[s] * 4);
        const uint32_t stB = st + A_STAGE_B;
#pragma unroll
        for (int s = 0; s < 4; ++s)
            cp16(stB + (uint32_t)(bm_[s] * ROWB + bk[s] * 16),
                 At + (size_t)(j0 + bm_[s]) * KDIM + kbase + bk[s] * 4);
        asm volatile("cp.async.commit_group;" ::: "memory");
    };

    float acc[4][4][4];
#pragma unroll
    for (int i = 0; i < 4; ++i)
#pragma unroll
        for (int j = 0; j < 4; ++j)
#pragma unroll
            for (int q = 0; q < 4; ++q) acc[i][j][q] = 0.0f;

    issue_chunk(0);
    issue_chunk(1);
    issue_chunk(2);

    for (int c = 0; c < NCH; ++c) {
        // guarantee group c complete (tail-exact clamp)
        if (c < NCH - 2)
            asm volatile("cp.async.wait_group 2;" ::: "memory");
        else if (c == NCH - 2)
            asm volatile("cp.async.wait_group 1;" ::: "memory");
        else
            asm volatile("cp.async.wait_group 0;" ::: "memory");
        __syncthreads();   // the ONLY barrier per chunk

        // stage (c+3)%4 == (c-1)%4: fully consumed before this barrier
        if (c + 3 < NCH) issue_chunk(c + 3);

        const uint32_t As = sbase + (c & (STAGES - 1)) * STAGE_B;
        const uint32_t Bs = As + A_STAGE_B;
#pragma unroll
        for (int ks = 0; ks < 4; ++ks) {
            uint32_t af[4][4];
#pragma unroll
            for (int i = 0; i < 4; ++i)
                ldsm4(af[i][0], af[i][1], af[i][2], af[i][3],
                      As + (uint32_t)(a_row + i * 16) * ROWB + (uint32_t)(ks * 32) + a_kb);
            uint32_t bf[4][2];
#pragma unroll
            for (int jj = 0; jj < 2; ++jj) {
                uint32_t r0, r1, r2, r3;
                ldsm4(r0, r1, r2, r3,
                      Bs + (uint32_t)(b_row + jj * 16) * ROWB + (uint32_t)(ks * 32) + b_kb);
                bf[2 * jj][0] = r0; bf[2 * jj][1] = r1;
                bf[2 * jj + 1][0] = r2; bf[2 * jj + 1][1] = r3;
            }
#pragma unroll
            for (int i = 0; i < 4; ++i)
#pragma unroll
                for (int j = 0; j < 4; ++j)
                    mma_tf32(acc[i][j], af[i], bf[j]);
        }
        // no trailing barrier: next iteration's sync provides the rendezvous
    }

    // epilogue: direct + mirrored (C symmetric)
    const int qrow = lane >> 2;
    const int qcol = (lane & 3) << 1;
#pragma unroll
    for (int i = 0; i < 4; ++i) {
        const int rm = i0 + wm * 64 + i * 16 + qrow;
#pragma unroll
        for (int j = 0; j < 4; ++j) {
            const int cn = j0 + wn * 32 + j * 8 + qcol;
            float2* p0 = reinterpret_cast<float2*>(out + (size_t)rm * NDIM + cn);
            float2* p1 = reinterpret_cast<float2*>(out + (size_t)(rm + 8) * NDIM + cn);
            *p0 = make_float2(acc[i][j][0], acc[i][j][1]);
            *p1 = make_float2(acc[i][j][2], acc[i][j][3]);
            out[(size_t)cn * NDIM + rm]           = acc[i][j][0];
            out[(size_t)(cn + 1) * NDIM + rm]     = acc[i][j][1];
            out[(size_t)cn * NDIM + rm + 8]       = acc[i][j][2];
            out[(size_t)(cn + 1) * NDIM + rm + 8] = acc[i][j][3];
        }
    }
}

extern "C" void kernel_launch(void* const* d_in, const int* in_sizes, int n_in,
                              void* d_out, int out_size) {
    const float* inp = (const float*)d_in[0];
    float* out = (float*)d_out;

    dim3 tgrid(NDIM / 32, KDIM / 32), tblk(32, 8);
    transpose_cvt_kernel<<<tgrid, tblk>>>(inp);

    cudaFuncSetAttribute(gram_mma_kernel,
                         cudaFuncAttributeMaxDynamicSharedMemorySize, SMEM_TOTAL);
    const int ntiles = 272;  // sum over bj<16 of (32 - 2*bj)
    gram_mma_kernel<<<ntiles, THREADS, SMEM_TOTAL>>>(out);
}

// round 10
// speedup vs baseline: 1.0863x; 1.0863x over previous
#include <cuda_runtime.h>
#include <cstdint>

// ============================================================================
// Gram matrix C = A^T A.  A: [8192, 4096] fp32 row-major. C: [4096, 4096] fp32.
// Pass 1: transpose+convert A -> At (tf32, [4096][8192]) in __device__ scratch.
// Pass 2: GEMM via mma.sync m16n8k8 tf32, cp.async 4-stage pipeline,
//         128x256 CTA tile, 256 threads (warp tile 64x64), lower-tri grid.
// R10: fragment double-buffering ACROSS the chunk barrier — HMMAs issue from
//      prefetched registers immediately post-barrier, breaking the phase-lock
//      that pinned tensor at ~57% in R3/R5/R9.
// ============================================================================

#define NDIM 4096
#define KDIM 8192
#define BM 128
#define BN 256
#define BK 32
#define NCH (KDIM / BK)       // 256 k-chunks
#define THREADS 256
#define ROWB 144              // 32 floats + 16B pad -> conflict-free LDSM/STS
#define STAGES 4

static constexpr int A_STAGE_B = BM * ROWB;             // 18432
static constexpr int B_STAGE_B = BN * ROWB;             // 36864
static constexpr int STAGE_B   = A_STAGE_B + B_STAGE_B; // 55296
static constexpr int SMEM_TOTAL = STAGES * STAGE_B;     // 221184

__device__ uint32_t g_AT[(size_t)NDIM * KDIM];          // 128MB tf32 scratch

__device__ __forceinline__ uint32_t smem_u32(const void* p) {
    uint32_t a;
    asm("{ .reg .u64 t; cvta.to.shared.u64 t, %1; cvt.u32.u64 %0, t; }"
        : "=r"(a) : "l"(p));
    return a;
}

__device__ __forceinline__ uint32_t f2tf32(float f) {
    uint32_t u;
    asm("cvt.rna.tf32.f32 %0, %1;" : "=r"(u) : "f"(f));
    return u;
}

__device__ __forceinline__ void ldsm4(uint32_t& r0, uint32_t& r1,
                                      uint32_t& r2, uint32_t& r3, uint32_t addr) {
    asm volatile("ldmatrix.sync.aligned.m8n8.x4.shared.b16 {%0,%1,%2,%3}, [%4];"
                 : "=r"(r0), "=r"(r1), "=r"(r2), "=r"(r3) : "r"(addr));
}

__device__ __forceinline__ void mma_tf32(float* c, const uint32_t* a, const uint32_t* b) {
    asm volatile(
        "mma.sync.aligned.m16n8k8.row.col.f32.tf32.tf32.f32 "
        "{%0,%1,%2,%3}, {%4,%5,%6,%7}, {%8,%9}, {%0,%1,%2,%3};"
        : "+f"(c[0]), "+f"(c[1]), "+f"(c[2]), "+f"(c[3])
        : "r"(a[0]), "r"(a[1]), "r"(a[2]), "r"(a[3]), "r"(b[0]), "r"(b[1]));
}

__device__ __forceinline__ void cp16(uint32_t dst, const void* src) {
    asm volatile("cp.async.cg.shared.global [%0], [%1], 16;"
                 :: "r"(dst), "l"(src) : "memory");
}

// ---------------------------------------------------------------------------
// Pass 1: At[n][k] = tf32(inp[k][n]).  32x32 smem tiles, block (32,8).
// ---------------------------------------------------------------------------
__global__ __launch_bounds__(256) void transpose_cvt_kernel(
        const float* __restrict__ inp) {
    __shared__ float tile[32][33];
    const int tx = threadIdx.x, ty = threadIdx.y;
    const int n0 = blockIdx.x * 32;
    const int k0 = blockIdx.y * 32;
#pragma unroll
    for (int j = 0; j < 4; ++j)
        tile[ty + j * 8][tx] = inp[(size_t)(k0 + ty + j * 8) * NDIM + n0 + tx];
    __syncthreads();
#pragma unroll
    for (int j = 0; j < 4; ++j)
        g_AT[(size_t)(n0 + ty + j * 8) * KDIM + k0 + tx] =
            f2tf32(tile[tx][ty + j * 8]);
}

// ---------------------------------------------------------------------------
// Pass 2: GEMM.  8 warps: wm = wid>>2 (2 x 64 rows), wn = wid&3 (4 x 64 cols)
// ---------------------------------------------------------------------------
__global__ __launch_bounds__(THREADS, 1)
void gram_mma_kernel(float* __restrict__ out) {
    extern __shared__ char smem[];
    const uint32_t sbase = smem_u32(smem);
    const int tid  = threadIdx.x;
    const int lane = tid & 31;
    const int wid  = tid >> 5;
    const int wm   = wid >> 2;      // 0..1  (m position, 64 rows)
    const int wn   = wid & 3;       // 0..3  (n position, 64 cols)

    // lower-triangle tile decode: (bi,bj) with bi >= 2*bj on 32(m) x 16(n) grid
    int t = (int)blockIdx.x, bj = 0;
    while (t >= 32 - 2 * bj) { t -= 32 - 2 * bj; ++bj; }
    const int bi = 2 * bj + t;
    const int i0 = bi * BM;
    const int j0 = bj * BN;

    // ldmatrix address components (tf32 frags via b16 x4)
    const int g = lane >> 3, r8 = lane & 7;
    const int a_row = wm * 64 + ((g & 1) << 3) + r8;
    const uint32_t a_kb = (uint32_t)((g >> 1) << 4);
    const int b_row = wn * 64 + ((g >> 1) << 3) + r8;
    const uint32_t b_kb = (uint32_t)((g & 1) << 4);

    // cp.async task decode: A = 1024 16B-chunks -> 4/thread, B = 2048 -> 8/thread
    int am[4], ak[4];
    int bm_[8], bk[8];
#pragma unroll
    for (int s = 0; s < 4; ++s) { int a = tid + THREADS * s; am[s] = a >> 3; ak[s] = a & 7; }
#pragma unroll
    for (int s = 0; s < 8; ++s) { int b = tid + THREADS * s; bm_[s] = b >> 3; bk[s] = b & 7; }

    const uint32_t* At = g_AT;

    auto issue_chunk = [&](int c) {
        const uint32_t st = sbase + (c & (STAGES - 1)) * STAGE_B;
        const size_t kbase = (size_t)c * BK;
#pragma unroll
        for (int s = 0; s < 4; ++s)
            cp16(st + (uint32_t)(am[s] * ROWB + ak[s] * 16),
                 At + (size_t)(i0 + am[s]) * KDIM + kbase + ak[s] * 4);
        const uint32_t stB = st + A_STAGE_B;
#pragma unroll
        for (int s = 0; s < 8; ++s)
            cp16(stB + (uint32_t)(bm_[s] * ROWB + bk[s] * 16),
                 At + (size_t)(j0 + bm_[s]) * KDIM + kbase + bk[s] * 4);
        asm volatile("cp.async.commit_group;" ::: "memory");
    };

    // fragment load for (chunk-stage, ks): af[4][4], bf[8][2]
    auto load_frags = [&](uint32_t af[4][4], uint32_t bf[8][2], int c, int ks) {
        const uint32_t As = sbase + (c & (STAGES - 1)) * STAGE_B;
        const uint32_t Bs = As + A_STAGE_B;
#pragma unroll
        for (int i = 0; i < 4; ++i)
            ldsm4(af[i][0], af[i][1], af[i][2], af[i][3],
                  As + (uint32_t)(a_row + i * 16) * ROWB + (uint32_t)(ks * 32) + a_kb);
#pragma unroll
        for (int jj = 0; jj < 4; ++jj) {
            uint32_t r0, r1, r2, r3;
            ldsm4(r0, r1, r2, r3,
                  Bs + (uint32_t)(b_row + jj * 16) * ROWB + (uint32_t)(ks * 32) + b_kb);
            bf[2 * jj][0] = r0; bf[2 * jj][1] = r1;
            bf[2 * jj + 1][0] = r2; bf[2 * jj + 1][1] = r3;
        }
    };

    float acc[4][8][4];
#pragma unroll
    for (int i = 0; i < 4; ++i)
#pragma unroll
        for (int j = 0; j < 8; ++j)
#pragma unroll
            for (int q = 0; q < 4; ++q) acc[i][j][q] = 0.0f;

    uint32_t af[2][4][4], bf[2][8][2];

    issue_chunk(0);
    issue_chunk(1);
    issue_chunk(2);
    asm volatile("cp.async.wait_group 2;" ::: "memory");   // chunk 0 ready
    __syncthreads();
    load_frags(af[0], bf[0], 0, 0);

    for (int c = 0; c < NCH; ++c) {
        // ks = 0..2: prefetch next ks frags, then MMA current
#pragma unroll
        for (int ks = 0; ks < 3; ++ks) {
            const int cur = ks & 1, nxt = cur ^ 1;
            load_frags(af[nxt], bf[nxt], c, ks + 1);
#pragma unroll
            for (int i = 0; i < 4; ++i)
#pragma unroll
                for (int j = 0; j < 8; ++j)
                    mma_tf32(acc[i][j], af[cur][i], bf[cur][j]);
        }

        // barrier point: chunk c+1 copies retired (own) + published (barrier);
        // all warps done reading stage (c-1)&3 -> safe to overwrite via c+3.
        if (c + 1 < NCH)
            asm volatile("cp.async.wait_group 1;" ::: "memory");
        else
            asm volatile("cp.async.wait_group 0;" ::: "memory");
        __syncthreads();
        if (c + 3 < NCH) issue_chunk(c + 3);

        // ks = 3: prefetch (c+1, ks=0) frags (safe post-barrier), MMA buf1
        if (c + 1 < NCH) load_frags(af[0], bf[0], c + 1, 0);
#pragma unroll
        for (int i = 0; i < 4; ++i)
#pragma unroll
            for (int j = 0; j < 8; ++j)
                mma_tf32(acc[i][j], af[1][i], bf[1][j]);
    }

    // epilogue: direct + mirrored (C symmetric)
    const int qrow = lane >> 2;
    const int qcol = (lane & 3) << 1;
#pragma unroll
    for (int i = 0; i < 4; ++i) {
        const int rm = i0 + wm * 64 + i * 16 + qrow;
#pragma unroll
        for (int j = 0; j < 8; ++j) {
            const int cn = j0 + wn * 64 + j * 8 + qcol;
            float2* p0 = reinterpret_cast<float2*>(out + (size_t)rm * NDIM + cn);
            float2* p1 = reinterpret_cast<float2*>(out + (size_t)(rm + 8) * NDIM + cn);
            *p0 = make_float2(acc[i][j][0], acc[i][j][1]);
            *p1 = make_float2(acc[i][j][2], acc[i][j][3]);
            out[(size_t)cn * NDIM + rm]           = acc[i][j][0];
            out[(size_t)(cn + 1) * NDIM + rm]     = acc[i][j][1];
            out[(size_t)cn * NDIM + rm + 8]       = acc[i][j][2];
            out[(size_t)(cn + 1) * NDIM + rm + 8] = acc[i][j][3];
        }
    }
}

extern "C" void kernel_launch(void* const* d_in, const int* in_sizes, int n_in,
                              void* d_out, int out_size) {
    const float* inp = (const float*)d_in[0];
    float* out = (float*)d_out;

    dim3 tgrid(NDIM / 32, KDIM / 32), tblk(32, 8);
    transpose_cvt_kernel<<<tgrid, tblk>>>(inp);

    cudaFuncSetAttribute(gram_mma_kernel,
                         cudaFuncAttributeMaxDynamicSharedMemorySize, SMEM_TOTAL);
    const int ntiles = 272;  // sum over bj<16 of (32 - 2*bj)
    gram_mma_kernel<<<ntiles, THREADS, SMEM_TOTAL>>>(out);
}

// round 13
// speedup vs baseline: 1.2499x; 1.1506x over previous
#include <cuda_runtime.h>
#include <cstdint>

// ============================================================================
// Gram matrix C = A^T A.  A: [8192, 4096] fp32 row-major. C: [4096, 4096] fp32.
// Pass 1: transpose+convert A -> At (tf32, [4096][8192]) in __device__ scratch.
// Pass 2: GEMM via mma.sync m16n8k8 tf32, cp.async 3-stage pipeline,
//         128x128 CTA tile, 128 threads (4 warps @ 64x64), lower-tri grid,
//         TWO CTAs per SM -> independent barrier domains overlap bubbles.
// R13 fix vs R12: cp.async wait_group BEFORE __syncthreads (per-thread retire
//         then CTA-wide publish) — R12 read frags copied by other threads
//         whose cp.asyncs were still in flight (rel_err 1.75e-3 race).
// ============================================================================

#define NDIM 4096
#define KDIM 8192
#define BM 128
#define BN 128
#define BK 32
#define NCH (KDIM / BK)       // 256 k-chunks
#define THREADS 128
#define ROWB 144              // 32 floats + 16B pad -> conflict-free LDSM/STS
#define STAGES 3

static constexpr int A_STAGE_B = BM * ROWB;             // 18432
static constexpr int B_STAGE_B = BN * ROWB;             // 18432
static constexpr int STAGE_B   = A_STAGE_B + B_STAGE_B; // 36864
static constexpr int SMEM_TOTAL = STAGES * STAGE_B;     // 110592 (x2 CTAs = 221184)

__device__ uint32_t g_AT[(size_t)NDIM * KDIM];          // 128MB tf32 scratch

__device__ __forceinline__ uint32_t smem_u32(const void* p) {
    uint32_t a;
    asm("{ .reg .u64 t; cvta.to.shared.u64 t, %1; cvt.u32.u64 %0, t; }"
        : "=r"(a) : "l"(p));
    return a;
}

__device__ __forceinline__ uint32_t f2tf32(float f) {
    uint32_t u;
    asm("cvt.rna.tf32.f32 %0, %1;" : "=r"(u) : "f"(f));
    return u;
}

__device__ __forceinline__ void ldsm4(uint32_t& r0, uint32_t& r1,
                                      uint32_t& r2, uint32_t& r3, uint32_t addr) {
    asm volatile("ldmatrix.sync.aligned.m8n8.x4.shared.b16 {%0,%1,%2,%3}, [%4];"
                 : "=r"(r0), "=r"(r1), "=r"(r2), "=r"(r3) : "r"(addr));
}

__device__ __forceinline__ void mma_tf32(float* c, const uint32_t* a, const uint32_t* b) {
    asm volatile(
        "mma.sync.aligned.m16n8k8.row.col.f32.tf32.tf32.f32 "
        "{%0,%1,%2,%3}, {%4,%5,%6,%7}, {%8,%9}, {%0,%1,%2,%3};"
        : "+f"(c[0]), "+f"(c[1]), "+f"(c[2]), "+f"(c[3])
        : "r"(a[0]), "r"(a[1]), "r"(a[2]), "r"(a[3]), "r"(b[0]), "r"(b[1]));
}

__device__ __forceinline__ void cp16(uint32_t dst, const void* src) {
    asm volatile("cp.async.cg.shared.global [%0], [%1], 16;"
                 :: "r"(dst), "l"(src) : "memory");
}

// ---------------------------------------------------------------------------
// Pass 1: At[n][k] = tf32(inp[k][n]).  32x32 smem tiles, block (32,8).
// ---------------------------------------------------------------------------
__global__ __launch_bounds__(256) void transpose_cvt_kernel(
        const float* __restrict__ inp) {
    __shared__ float tile[32][33];
    const int tx = threadIdx.x, ty = threadIdx.y;
    const int n0 = blockIdx.x * 32;
    const int k0 = blockIdx.y * 32;
#pragma unroll
    for (int j = 0; j < 4; ++j)
        tile[ty + j * 8][tx] = inp[(size_t)(k0 + ty + j * 8) * NDIM + n0 + tx];
    __syncthreads();
#pragma unroll
    for (int j = 0; j < 4; ++j)
        g_AT[(size_t)(n0 + ty + j * 8) * KDIM + k0 + tx] =
            f2tf32(tile[tx][ty + j * 8]);
}

// ---------------------------------------------------------------------------
// Pass 2: GEMM.  4 warps: wm = wid>>1 (2 x 64 rows), wn = wid&1 (2 x 64 cols)
// ---------------------------------------------------------------------------
__global__ __launch_bounds__(THREADS, 2)
void gram_mma_kernel(float* __restrict__ out) {
    extern __shared__ char smem[];
    const uint32_t sbase = smem_u32(smem);
    const int tid  = threadIdx.x;
    const int lane = tid & 31;
    const int wid  = tid >> 5;
    const int wm   = wid >> 1;      // 0..1  (m position, 64 rows)
    const int wn   = wid & 1;       // 0..1  (n position, 64 cols)

    // lower-triangle tile decode: (bi,bj) with bi >= bj on 32x32 grid of 128-tiles
    int t = (int)blockIdx.x, bj = 0;
    while (t >= 32 - bj) { t -= 32 - bj; ++bj; }
    const int bi = bj + t;
    const int i0 = bi * BM;
    const int j0 = bj * BN;

    // ldmatrix address components (tf32 frags via b16 x4)
    const int g = lane >> 3, r8 = lane & 7;
    const int a_row = wm * 64 + ((g & 1) << 3) + r8;
    const uint32_t a_kb = (uint32_t)((g >> 1) << 4);
    const int b_row = wn * 64 + ((g >> 1) << 3) + r8;
    const uint32_t b_kb = (uint32_t)((g & 1) << 4);

    // cp.async task decode: A = 1024 16B-chunks (128m x 8kg) -> 8/thread, B same.
    int am[8], ak[8];
#pragma unroll
    for (int s = 0; s < 8; ++s) { int a = tid + THREADS * s; am[s] = a >> 3; ak[s] = a & 7; }

    const uint32_t* At = g_AT;

    auto issue_chunk = [&](int c) {
        const uint32_t st = sbase + (c % STAGES) * STAGE_B;
        const size_t kbase = (size_t)c * BK;
#pragma unroll
        for (int s = 0; s < 8; ++s)
            cp16(st + (uint32_t)(am[s] * ROWB + ak[s] * 16),
                 At + (size_t)(i0 + am[s]) * KDIM + kbase + ak[s] * 4);
        const uint32_t stB = st + A_STAGE_B;
#pragma unroll
        for (int s = 0; s < 8; ++s)
            cp16(stB + (uint32_t)(am[s] * ROWB + ak[s] * 16),
                 At + (size_t)(j0 + am[s]) * KDIM + kbase + ak[s] * 4);
        asm volatile("cp.async.commit_group;" ::: "memory");
    };

    // fragment load for (chunk, ks): af[4][4], bf[8][2]
    auto load_frags = [&](uint32_t af[4][4], uint32_t bf[8][2], int c, int ks) {
        const uint32_t As = sbase + (c % STAGES) * STAGE_B;
        const uint32_t Bs = As + A_STAGE_B;
#pragma unroll
        for (int i = 0; i < 4; ++i)
            ldsm4(af[i][0], af[i][1], af[i][2], af[i][3],
                  As + (uint32_t)(a_row + i * 16) * ROWB + (uint32_t)(ks * 32) + a_kb);
#pragma unroll
        for (int jj = 0; jj < 4; ++jj) {
            uint32_t r0, r1, r2, r3;
            ldsm4(r0, r1, r2, r3,
                  Bs + (uint32_t)(b_row + jj * 16) * ROWB + (uint32_t)(ks * 32) + b_kb);
            bf[2 * jj][0] = r0; bf[2 * jj][1] = r1;
            bf[2 * jj + 1][0] = r2; bf[2 * jj + 1][1] = r3;
        }
    };

    float acc[4][8][4];
#pragma unroll
    for (int i = 0; i < 4; ++i)
#pragma unroll
        for (int j = 0; j < 8; ++j)
#pragma unroll
            for (int q = 0; q < 4; ++q) acc[i][j][q] = 0.0f;

    uint32_t af[2][4][4], bf[2][8][2];

    issue_chunk(0);
    issue_chunk(1);
    asm volatile("cp.async.wait_group 1;" ::: "memory");   // chunk 0 retired (own)
    __syncthreads();                                       // ...and published
    load_frags(af[0], bf[0], 0, 0);

    for (int c = 0; c < NCH; ++c) {
        // ks = 0..2: prefetch next ks frags from chunk c, then MMA current
#pragma unroll
        for (int ks = 0; ks < 3; ++ks) {
            const int cur = ks & 1, nxt = cur ^ 1;
            load_frags(af[nxt], bf[nxt], c, ks + 1);
#pragma unroll
            for (int i = 0; i < 4; ++i)
#pragma unroll
                for (int j = 0; j < 8; ++j)
                    mma_tf32(acc[i][j], af[cur][i], bf[cur][j]);
        }

        // ORDER MATTERS: (1) wait_group 0 — pending = {c+1} only, so every
        // thread's chunk-(c+1) copies are retired; (2) __syncthreads — makes
        // them visible CTA-wide AND proves all warps finished reading stage
        // (c-1)%3; (3) only then overwrite that stage with chunk c+2.
        asm volatile("cp.async.wait_group 0;" ::: "memory");
        __syncthreads();
        if (c + 2 < NCH) issue_chunk(c + 2);

        // ks = 3: prefetch (c+1, ks=0) frags (now safe), MMA pre-barrier buffer
        if (c + 1 < NCH) load_frags(af[0], bf[0], c + 1, 0);
#pragma unroll
        for (int i = 0; i < 4; ++i)
#pragma unroll
            for (int j = 0; j < 8; ++j)
                mma_tf32(acc[i][j], af[1][i], bf[1][j]);
    }

    // epilogue: direct + mirrored (C symmetric; diag tiles double-write equal values)
    const int qrow = lane >> 2;
    const int qcol = (lane & 3) << 1;
#pragma unroll
    for (int i = 0; i < 4; ++i) {
        const int rm = i0 + wm * 64 + i * 16 + qrow;
#pragma unroll
        for (int j = 0; j < 8; ++j) {
            const int cn = j0 + wn * 64 + j * 8 + qcol;
            float2* p0 = reinterpret_cast<float2*>(out + (size_t)rm * NDIM + cn);
            float2* p1 = reinterpret_cast<float2*>(out + (size_t)(rm + 8) * NDIM + cn);
            *p0 = make_float2(acc[i][j][0], acc[i][j][1]);
            *p1 = make_float2(acc[i][j][2], acc[i][j][3]);
            out[(size_t)cn * NDIM + rm]           = acc[i][j][0];
            out[(size_t)(cn + 1) * NDIM + rm]     = acc[i][j][1];
            out[(size_t)cn * NDIM + rm + 8]       = acc[i][j][2];
            out[(size_t)(cn + 1) * NDIM + rm + 8] = acc[i][j][3];
        }
    }
}

extern "C" void kernel_launch(void* const* d_in, const int* in_sizes, int n_in,
                              void* d_out, int out_size) {
    const float* inp = (const float*)d_in[0];
    float* out = (float*)d_out;

    dim3 tgrid(NDIM / 32, KDIM / 32), tblk(32, 8);
    transpose_cvt_kernel<<<tgrid, tblk>>>(inp);

    cudaFuncSetAttribute(gram_mma_kernel,
                         cudaFuncAttributeMaxDynamicSharedMemorySize, SMEM_TOTAL);
    const int ntiles = 32 * 33 / 2;  // 528 lower-triangle 128x128 tiles
    gram_mma_kernel<<<ntiles, THREADS, SMEM_TOTAL>>>(out);
}